// round 1
// baseline (speedup 1.0000x reference)
#include <cuda_runtime.h>

#define HWSZ 262144           // 512*512
#define IMG_W 512
#define IMG_H 512
#define NB 8

// NHWC4 scratch: [b][h][w] -> float4(c0,c1,c2,0). 33.5 MB, fits in L2.
__device__ float4 g_xt[NB * IMG_H * IMG_W];

// ---------------------------------------------------------------------------
// Kernel 1: NCHW -> NHWC4 transpose
// ---------------------------------------------------------------------------
__global__ __launch_bounds__(256) void k_transpose(const float* __restrict__ x) {
    int idx = blockIdx.x * 256 + threadIdx.x;   // b*HWSZ + hw, grid sized exactly
    int b  = idx >> 18;
    int hw = idx & (HWSZ - 1);
    const float* xb = x + (size_t)b * 3 * HWSZ + hw;
    g_xt[idx] = make_float4(xb[0], xb[HWSZ], xb[2 * HWSZ], 0.f);
}

// ---------------------------------------------------------------------------
// Bilinear sample (zero padding, align_corners=False) fused with w2 dot3.
// Whole-sample OOB early-out: nonzero only if x0,y0 in [-1,511].
// ---------------------------------------------------------------------------
__device__ __forceinline__ void sample_acc(int base_b, float gx, float gy,
                                           float4 wv, float& acc) {
    float ix = fmaf(gx, 256.f, 255.5f);   // ((gx+1)*512 - 1)*0.5
    float iy = fmaf(gy, 256.f, 255.5f);
    float fx0 = floorf(ix), fy0 = floorf(iy);
    int x0 = (int)fx0, y0 = (int)fy0;
    if ((unsigned)(x0 + 1) > 512u || (unsigned)(y0 + 1) > 512u) return;

    float wx1 = ix - fx0, wy1 = iy - fy0;
    float wx0 = 1.f - wx1, wy0 = 1.f - wy1;
    bool vx0 = (x0 >= 0),  vx1 = (x0 < 511);
    bool vy0 = (y0 >= 0),  vy1 = (y0 < 511);

    const float4* __restrict__ xt = g_xt;
    int r0 = base_b + (y0 << 9) + x0;
    float4 z4 = make_float4(0.f, 0.f, 0.f, 0.f);
    float4 v00 = (vy0 && vx0) ? __ldg(xt + r0)       : z4;
    float4 v01 = (vy0 && vx1) ? __ldg(xt + r0 + 1)   : z4;
    float4 v10 = (vy1 && vx0) ? __ldg(xt + r0 + 512) : z4;
    float4 v11 = (vy1 && vx1) ? __ldg(xt + r0 + 513) : z4;

    float s0 = wy0 * (wx0 * v00.x + wx1 * v01.x) + wy1 * (wx0 * v10.x + wx1 * v11.x);
    float s1 = wy0 * (wx0 * v00.y + wx1 * v01.y) + wy1 * (wx0 * v10.y + wx1 * v11.y);
    float s2 = wy0 * (wx0 * v00.z + wx1 * v01.z) + wy1 * (wx0 * v10.z + wx1 * v11.z);

    acc = fmaf(s0, wv.x, acc);
    acc = fmaf(s1, wv.y, acc);
    acc = fmaf(s2, wv.z, acc);
}

// ---------------------------------------------------------------------------
// Kernel 2: fused conv3x3 + sigmoid + deformable sampling + grouped 1x1 + relu
// One thread per output pixel (computes all 3 output channels).
// grid = (W/256, H, B), block = 256 along w.
// ---------------------------------------------------------------------------
__global__ __launch_bounds__(256) void k_seesaw(const float* __restrict__ w1,
                                                const float* __restrict__ b1,
                                                const float* __restrict__ w2,
                                                const float* __restrict__ b2,
                                                float* __restrict__ out) {
    __shared__ float4 s_w1v[9][8];  // [pos][o] = (w_c0, w_c1, w_c2, 0)
    __shared__ float  s_b1[8];
    __shared__ float4 s_w2v[9];     // w2 reinterpreted as [k][c] (see derivation)
    __shared__ float  s_b2[4];

    int t = threadIdx.x;
    if (t < 72) {
        int o = t / 9, pos = t % 9;
        s_w1v[pos][o] = make_float4(w1[o * 27 + pos],
                                    w1[o * 27 + 9 + pos],
                                    w1[o * 27 + 18 + pos], 0.f);
    } else if (t < 80) {
        s_b1[t - 72] = b1[t - 72];
    } else if (t < 89) {
        int k = t - 80;
        s_w2v[k] = make_float4(w2[3 * k], w2[3 * k + 1], w2[3 * k + 2], 0.f);
    } else if (t < 92) {
        s_b2[t - 89] = b2[t - 89];
    }
    __syncthreads();

    int w = blockIdx.x * 256 + t;
    int h = blockIdx.y;
    int b = blockIdx.z;
    int base_b = b << 18;                       // b*HWSZ in float4 units
    const float4* __restrict__ xt = g_xt;

    // ---- conv3x3 over NHWC4 neighborhood ----
    float z[8];
#pragma unroll
    for (int o = 0; o < 8; o++) z[o] = s_b1[o];

    float4 zero4 = make_float4(0.f, 0.f, 0.f, 0.f);
#pragma unroll
    for (int di = 0; di < 3; di++) {
        int hh = h + di - 1;
        bool vh = ((unsigned)hh < 512u);
#pragma unroll
        for (int dj = 0; dj < 3; dj++) {
            int ww = w + dj - 1;
            bool v = vh && ((unsigned)ww < 512u);
            float4 p = v ? __ldg(xt + base_b + (hh << 9) + ww) : zero4;
            int pos = di * 3 + dj;
#pragma unroll
            for (int o = 0; o < 8; o++) {
                float4 wv = s_w1v[pos][o];
                z[o] = fmaf(p.x, wv.x, fmaf(p.y, wv.y, fmaf(p.z, wv.z, z[o])));
            }
        }
    }

    // ---- sigmoid -> 8 offsets ----
    float s[8];
#pragma unroll
    for (int o = 0; o < 8; o++)
        s[o] = __fdividef(1.f, 1.f + __expf(-z[o]));

    float hb = (float)h * (1.f / 511.f);
    float wb = (float)w * (1.f / 511.f);

    // ---- 9 samples; channel-group mapping: out channel g uses k in {3g..3g+2},
    //      w2 re-reads as [k][c] ----
    float a0 = 0.f, a1 = 0.f, a2 = 0.f;
    sample_acc(base_b, hb + s[0], wb + s[1], s_w2v[0], a0);        // k=0
    sample_acc(base_b, hb + s[2], wb + s[3], s_w2v[1], a0);        // k=1
    sample_acc(base_b, hb + s[4], wb + s[5], s_w2v[2], a0);        // k=2
    sample_acc(base_b, hb + s[6], wb + s[7], s_w2v[3], a1);        // k=3
    sample_acc(base_b, hb,        wb,        s_w2v[4], a1);        // k=4 (center)
    sample_acc(base_b, hb + 2.f - s[0], wb + 2.f - s[1], s_w2v[5], a1);  // k=5
    sample_acc(base_b, hb + 2.f - s[2], wb + 2.f - s[3], s_w2v[6], a2);  // k=6
    sample_acc(base_b, hb + 2.f - s[4], wb + 2.f - s[5], s_w2v[7], a2);  // k=7
    sample_acc(base_b, hb + 2.f - s[6], wb + 2.f - s[7], s_w2v[8], a2);  // k=8

    // ---- bias + relu, NCHW output ----
    int po = b * 3 * HWSZ + (h << 9) + w;
    out[po]            = fmaxf(a0 + s_b2[0], 0.f);
    out[po + HWSZ]     = fmaxf(a1 + s_b2[1], 0.f);
    out[po + 2 * HWSZ] = fmaxf(a2 + s_b2[2], 0.f);
}

// ---------------------------------------------------------------------------
extern "C" void kernel_launch(void* const* d_in, const int* in_sizes, int n_in,
                              void* d_out, int out_size) {
    const float* x  = (const float*)d_in[0];
    const float* w1 = (const float*)d_in[1];
    const float* b1 = (const float*)d_in[2];
    const float* w2 = (const float*)d_in[3];
    const float* b2 = (const float*)d_in[4];
    float* out = (float*)d_out;

    k_transpose<<<NB * HWSZ / 256, 256>>>(x);
    k_seesaw<<<dim3(IMG_W / 256, IMG_H, NB), 256>>>(w1, b1, w2, b2, out);
}

// round 2
// speedup vs baseline: 1.0377x; 1.0377x over previous
#include <cuda_runtime.h>

#define HWSZ 262144           // 512*512
#define IMG_W 512
#define IMG_H 512
#define NB 8

// NHWC4 scratch (conv layout): [b][h][w] -> float4(c0,c1,c2,0). 33.5 MB.
__device__ float4 g_xt[NB * IMG_H * IMG_W];
// Transposed copy (sample layout): [b][x][y] -> same float4. 33.5 MB.
// y (image row) is the FAST dim; lanes vary along y in the sample path.
__device__ float4 g_xtT[NB * IMG_H * IMG_W];

// ---------------------------------------------------------------------------
// Kernel 1: NCHW -> NHWC4 (both layouts), tiled so all GMEM ops coalesce.
// grid (16,16,8), block (32,8); each thread does 4 rows of a 32x32 tile.
// ---------------------------------------------------------------------------
__global__ __launch_bounds__(256) void k_transpose(const float* __restrict__ x) {
    __shared__ float4 tile[32][33];
    int b  = blockIdx.z;
    int h0 = blockIdx.y << 5;
    int w0 = blockIdx.x << 5;
    int tx = threadIdx.x, ty = threadIdx.y;
    const float* xb = x + (size_t)b * 3 * HWSZ;
    int base_b = b << 18;

#pragma unroll
    for (int r = 0; r < 4; r++) {
        int rr = ty + (r << 3);
        int hw = ((h0 + rr) << 9) + (w0 + tx);
        float4 v = make_float4(xb[hw], xb[HWSZ + hw], xb[2 * HWSZ + hw], 0.f);
        g_xt[base_b + hw] = v;              // coalesced (w fast)
        tile[rr][tx] = v;
    }
    __syncthreads();
#pragma unroll
    for (int r = 0; r < 4; r++) {
        int rr = ty + (r << 3);
        // T[b][x = w0+rr][y = h0+tx]  -> lanes along y fast dim: coalesced
        g_xtT[base_b + ((w0 + rr) << 9) + (h0 + tx)] = tile[tx][rr];
    }
}

// ---------------------------------------------------------------------------
// Bilinear sample from TRANSPOSED layout, fused with w2 dot3.
// gx -> column (slow dim), gy -> row (fast dim, varies per lane).
// ---------------------------------------------------------------------------
__device__ __forceinline__ void sample_acc(int base_b, float gx, float gy,
                                           float4 wv, float& acc) {
    float ix = fmaf(gx, 256.f, 255.5f);   // ((g+1)*512 - 1)*0.5
    float iy = fmaf(gy, 256.f, 255.5f);
    float fx0 = floorf(ix), fy0 = floorf(iy);
    int x0 = (int)fx0, y0 = (int)fy0;
    if ((unsigned)(x0 + 1) > 512u || (unsigned)(y0 + 1) > 512u) return;

    float wx1 = ix - fx0, wy1 = iy - fy0;
    float wx0 = 1.f - wx1, wy0 = 1.f - wy1;
    bool vx0 = (x0 >= 0),  vx1 = (x0 < 511);
    bool vy0 = (y0 >= 0),  vy1 = (y0 < 511);

    const float4* __restrict__ xt = g_xtT;
    int r0 = base_b + (x0 << 9) + y0;     // x slow, y fast
    float4 z4 = make_float4(0.f, 0.f, 0.f, 0.f);
    float4 v00 = (vy0 && vx0) ? __ldg(xt + r0)       : z4;  // (y0  , x0  )
    float4 v01 = (vy0 && vx1) ? __ldg(xt + r0 + 512) : z4;  // (y0  , x0+1)
    float4 v10 = (vy1 && vx0) ? __ldg(xt + r0 + 1)   : z4;  // (y0+1, x0  )
    float4 v11 = (vy1 && vx1) ? __ldg(xt + r0 + 513) : z4;  // (y0+1, x0+1)

    float s0 = wy0 * (wx0 * v00.x + wx1 * v01.x) + wy1 * (wx0 * v10.x + wx1 * v11.x);
    float s1 = wy0 * (wx0 * v00.y + wx1 * v01.y) + wy1 * (wx0 * v10.y + wx1 * v11.y);
    float s2 = wy0 * (wx0 * v00.z + wx1 * v01.z) + wy1 * (wx0 * v10.z + wx1 * v11.z);

    acc = fmaf(s0, wv.x, acc);
    acc = fmaf(s1, wv.y, acc);
    acc = fmaf(s2, wv.z, acc);
}

// ---------------------------------------------------------------------------
// Kernel 2: fused conv3x3 + sigmoid + deformable sampling + grouped 1x1 + relu
// One thread per output pixel. grid = (W/256, H, B), block = 256 along w.
// ---------------------------------------------------------------------------
__global__ __launch_bounds__(256) void k_seesaw(const float* __restrict__ w1,
                                                const float* __restrict__ b1,
                                                const float* __restrict__ w2,
                                                const float* __restrict__ b2,
                                                float* __restrict__ out) {
    __shared__ float4 s_w1v[9][8];  // [pos][o] = (w_c0, w_c1, w_c2, 0)
    __shared__ float  s_b1[8];
    __shared__ float4 s_w2v[9];     // w2 reinterpreted as [k][c]
    __shared__ float  s_b2[4];

    int t = threadIdx.x;
    if (t < 72) {
        int o = t / 9, pos = t % 9;
        s_w1v[pos][o] = make_float4(w1[o * 27 + pos],
                                    w1[o * 27 + 9 + pos],
                                    w1[o * 27 + 18 + pos], 0.f);
    } else if (t < 80) {
        s_b1[t - 72] = b1[t - 72];
    } else if (t < 89) {
        int k = t - 80;
        s_w2v[k] = make_float4(w2[3 * k], w2[3 * k + 1], w2[3 * k + 2], 0.f);
    } else if (t < 92) {
        s_b2[t - 89] = b2[t - 89];
    }
    __syncthreads();

    int w = blockIdx.x * 256 + t;
    int h = blockIdx.y;
    int b = blockIdx.z;
    int base_b = b << 18;
    const float4* __restrict__ xt = g_xt;

    // ---- conv3x3 over NHWC4 neighborhood (original layout, coalesced) ----
    float z[8];
#pragma unroll
    for (int o = 0; o < 8; o++) z[o] = s_b1[o];

    float4 zero4 = make_float4(0.f, 0.f, 0.f, 0.f);
#pragma unroll
    for (int di = 0; di < 3; di++) {
        int hh = h + di - 1;
        bool vh = ((unsigned)hh < 512u);
#pragma unroll
        for (int dj = 0; dj < 3; dj++) {
            int ww = w + dj - 1;
            bool v = vh && ((unsigned)ww < 512u);
            float4 p = v ? __ldg(xt + base_b + (hh << 9) + ww) : zero4;
            int pos = di * 3 + dj;
#pragma unroll
            for (int o = 0; o < 8; o++) {
                float4 wv = s_w1v[pos][o];
                z[o] = fmaf(p.x, wv.x, fmaf(p.y, wv.y, fmaf(p.z, wv.z, z[o])));
            }
        }
    }

    // ---- sigmoid -> 8 offsets ----
    float s[8];
#pragma unroll
    for (int o = 0; o < 8; o++)
        s[o] = __fdividef(1.f, 1.f + __expf(-z[o]));

    float hb = (float)h * (1.f / 511.f);
    float wb = (float)w * (1.f / 511.f);

    // ---- 9 samples; out channel g uses k in {3g..3g+2} ----
    float a0 = 0.f, a1 = 0.f, a2 = 0.f;
    sample_acc(base_b, hb + s[0], wb + s[1], s_w2v[0], a0);               // k=0
    sample_acc(base_b, hb + s[2], wb + s[3], s_w2v[1], a0);               // k=1
    sample_acc(base_b, hb + s[4], wb + s[5], s_w2v[2], a0);               // k=2
    sample_acc(base_b, hb + s[6], wb + s[7], s_w2v[3], a1);               // k=3
    sample_acc(base_b, hb,        wb,        s_w2v[4], a1);               // k=4
    sample_acc(base_b, hb + 2.f - s[0], wb + 2.f - s[1], s_w2v[5], a1);   // k=5
    sample_acc(base_b, hb + 2.f - s[2], wb + 2.f - s[3], s_w2v[6], a2);   // k=6
    sample_acc(base_b, hb + 2.f - s[4], wb + 2.f - s[5], s_w2v[7], a2);   // k=7
    sample_acc(base_b, hb + 2.f - s[6], wb + 2.f - s[7], s_w2v[8], a2);   // k=8

    // ---- bias + relu, NCHW output ----
    int po = b * 3 * HWSZ + (h << 9) + w;
    out[po]            = fmaxf(a0 + s_b2[0], 0.f);
    out[po + HWSZ]     = fmaxf(a1 + s_b2[1], 0.f);
    out[po + 2 * HWSZ] = fmaxf(a2 + s_b2[2], 0.f);
}

// ---------------------------------------------------------------------------
extern "C" void kernel_launch(void* const* d_in, const int* in_sizes, int n_in,
                              void* d_out, int out_size) {
    const float* x  = (const float*)d_in[0];
    const float* w1 = (const float*)d_in[1];
    const float* b1 = (const float*)d_in[2];
    const float* w2 = (const float*)d_in[3];
    const float* b2 = (const float*)d_in[4];
    float* out = (float*)d_out;

    k_transpose<<<dim3(16, 16, NB), dim3(32, 8)>>>(x);
    k_seesaw<<<dim3(IMG_W / 256, IMG_H, NB), 256>>>(w1, b1, w2, b2, out);
}

// round 3
// speedup vs baseline: 1.3389x; 1.2903x over previous
#include <cuda_runtime.h>
#include <cuda_fp16.h>

#define HWSZ 262144           // 512*512
#define NB 8

// fp32 NHWC4 [b][h][w] for conv3x3 (33.5 MB).
__device__ float4 g_xt[NB * HWSZ];
// fp16 row-pair buffer for sampling: [b][x:513][y:512], 16B element =
// {c0,c1,c2,pad}(row y) ++ {c0,c1,c2,pad}(row y+1), halves.
// Column x=512 and the row-512 half of y=511 stay ZERO (zero-init / explicit)
// so boundary masking is free. 33.6 MB.
__device__ uint4 g_xh[NB * 513 * 512];

// ---------------------------------------------------------------------------
// Kernel 1: build both buffers. grid (16,16,8), block (32,8).
// ---------------------------------------------------------------------------
__global__ __launch_bounds__(256) void k_prep(const float* __restrict__ x) {
    __shared__ float4 tile[33][33];   // [row-in-tile][col-in-tile]
    int b = blockIdx.z, h0 = blockIdx.y << 5, w0 = blockIdx.x << 5;
    int tx = threadIdx.x, ty = threadIdx.y;
    const float* xb = x + (size_t)b * 3 * HWSZ;

#pragma unroll
    for (int r = 0; r < 5; r++) {
        int rr = ty + (r << 3);
        if (rr < 33) {
            int hh = h0 + rr;
            float4 v = make_float4(0.f, 0.f, 0.f, 0.f);
            if (hh < 512) {
                int hw = (hh << 9) + w0 + tx;
                v = make_float4(xb[hw], xb[HWSZ + hw], xb[2 * HWSZ + hw], 0.f);
                if (rr < 32) g_xt[(b << 18) + hw] = v;   // coalesced (w fast)
            }
            tile[rr][tx] = v;
        }
    }
    __syncthreads();
#pragma unroll
    for (int r = 0; r < 4; r++) {
        int rr = ty + (r << 3);                 // col offset -> x = w0+rr
        float4 a = tile[tx][rr];                // row y   = h0+tx
        float4 c = tile[tx + 1][rr];            // row y+1
        __half2 p0 = __floats2half2_rn(a.x, a.y);
        __half2 p1 = __floats2half2_rn(a.z, 0.f);
        __half2 p2 = __floats2half2_rn(c.x, c.y);
        __half2 p3 = __floats2half2_rn(c.z, 0.f);
        uint4 u;
        u.x = *reinterpret_cast<unsigned*>(&p0);
        u.y = *reinterpret_cast<unsigned*>(&p1);
        u.z = *reinterpret_cast<unsigned*>(&p2);
        u.w = *reinterpret_cast<unsigned*>(&p3);
        g_xh[((b * 513 + (w0 + rr)) << 9) + (h0 + tx)] = u;  // coalesced (y fast)
    }
}

// ---------------------------------------------------------------------------
// Bilinear sample: 2 scattered 16B loads (row-pair packing). No masks needed:
// zero padding in g_xh reproduces grid_sample's zero OOB exactly.
// ---------------------------------------------------------------------------
__device__ __forceinline__ void samp(const uint4* __restrict__ colb,
                                     float gx, float gy, float4 wv, float& acc) {
    float ix = fmaf(gx, 256.f, 255.5f);   // ((g+1)*512-1)*0.5 ; always > 255.5
    float iy = fmaf(gy, 256.f, 255.5f);
    if (ix >= 512.f || iy >= 512.f) return;   // whole-sample OOB (upper only)
    int x0 = (int)ix, y0 = (int)iy;           // trunc == floor (positive)
    float wx1 = ix - (float)x0, wy1 = iy - (float)y0;
    float wx0 = 1.f - wx1, wy0 = 1.f - wy1;

    const uint4* c0 = colb + (x0 << 9) + y0;
    uint4 qa = __ldg(c0);          // column x0  : rows y0,y0+1
    uint4 qb = __ldg(c0 + 512);    // column x0+1 (x0=511 -> zero column)

    float2 a01 = __half22float2(*reinterpret_cast<__half2*>(&qa.x));
    float2 a2_ = __half22float2(*reinterpret_cast<__half2*>(&qa.y));
    float2 a01b = __half22float2(*reinterpret_cast<__half2*>(&qa.z));
    float2 a2b  = __half22float2(*reinterpret_cast<__half2*>(&qa.w));
    float2 b01 = __half22float2(*reinterpret_cast<__half2*>(&qb.x));
    float2 b2_ = __half22float2(*reinterpret_cast<__half2*>(&qb.y));
    float2 b01b = __half22float2(*reinterpret_cast<__half2*>(&qb.z));
    float2 b2b  = __half22float2(*reinterpret_cast<__half2*>(&qb.w));

    float cA0 = wy0 * a01.x + wy1 * a01b.x;
    float cA1 = wy0 * a01.y + wy1 * a01b.y;
    float cA2 = wy0 * a2_.x + wy1 * a2b.x;
    float cB0 = wy0 * b01.x + wy1 * b01b.x;
    float cB1 = wy0 * b01.y + wy1 * b01b.y;
    float cB2 = wy0 * b2_.x + wy1 * b2b.x;

    float s0 = wx0 * cA0 + wx1 * cB0;
    float s1 = wx0 * cA1 + wx1 * cB1;
    float s2 = wx0 * cA2 + wx1 * cB2;
    acc = fmaf(s0, wv.x, fmaf(s1, wv.y, fmaf(s2, wv.z, acc)));
}

// ---------------------------------------------------------------------------
// Kernel 2: fused everything. 2 pixels/thread along w.
// grid (2, 512, 8), block 128. Samples k=5..8 (symmetric) are provably OOB:
// channel2 = relu(b2[2]); channel1 = k3 + center.
// ---------------------------------------------------------------------------
__global__ __launch_bounds__(128) void k_seesaw(const float* __restrict__ w1,
                                                const float* __restrict__ b1,
                                                const float* __restrict__ w2,
                                                const float* __restrict__ b2,
                                                float* __restrict__ out) {
    __shared__ float4 s_w1v[9][8];  // [pos][o] = (w_c0,w_c1,w_c2,0)
    __shared__ float  s_b1[8];
    __shared__ float4 s_w2v[5];     // k = 0..4 only
    __shared__ float  s_b2[4];

    int t = threadIdx.x;
    if (t < 72) {
        int o = t / 9, pos = t % 9;
        s_w1v[pos][o] = make_float4(w1[o * 27 + pos],
                                    w1[o * 27 + 9 + pos],
                                    w1[o * 27 + 18 + pos], 0.f);
    } else if (t < 80) {
        s_b1[t - 72] = b1[t - 72];
    } else if (t < 85) {
        int k = t - 80;
        s_w2v[k] = make_float4(w2[3 * k], w2[3 * k + 1], w2[3 * k + 2], 0.f);
    } else if (t < 88) {
        s_b2[t - 85] = b2[t - 85];
    }
    __syncthreads();

    int w = (blockIdx.x << 8) + (t << 1);
    int h = blockIdx.y;
    int b = blockIdx.z;
    int base_b = b << 18;
    const float4* __restrict__ xt = g_xt;

    // ---- conv3x3, 2 pixels: cols w-1..w+2 ----
    float z0[8], z1[8];
#pragma unroll
    for (int o = 0; o < 8; o++) { z0[o] = s_b1[o]; z1[o] = s_b1[o]; }

    float4 zero4 = make_float4(0.f, 0.f, 0.f, 0.f);
#pragma unroll
    for (int di = 0; di < 3; di++) {
        int hh = h + di - 1;
        bool vh = ((unsigned)hh < 512u);
        int rbase = base_b + (hh << 9) + w;
        float4 p0 = (vh && w > 0)    ? __ldg(xt + rbase - 1) : zero4;
        float4 p1 = vh               ? __ldg(xt + rbase)     : zero4;
        float4 p2 = vh               ? __ldg(xt + rbase + 1) : zero4;
        float4 p3 = (vh && w < 510)  ? __ldg(xt + rbase + 2) : zero4;
        int pos = di * 3;
#pragma unroll
        for (int o = 0; o < 8; o++) {
            float4 wa = s_w1v[pos][o], wb = s_w1v[pos + 1][o], wc = s_w1v[pos + 2][o];
            z0[o] = fmaf(p0.x, wa.x, fmaf(p0.y, wa.y, fmaf(p0.z, wa.z, z0[o])));
            z0[o] = fmaf(p1.x, wb.x, fmaf(p1.y, wb.y, fmaf(p1.z, wb.z, z0[o])));
            z0[o] = fmaf(p2.x, wc.x, fmaf(p2.y, wc.y, fmaf(p2.z, wc.z, z0[o])));
            z1[o] = fmaf(p1.x, wa.x, fmaf(p1.y, wa.y, fmaf(p1.z, wa.z, z1[o])));
            z1[o] = fmaf(p2.x, wb.x, fmaf(p2.y, wb.y, fmaf(p2.z, wb.z, z1[o])));
            z1[o] = fmaf(p3.x, wc.x, fmaf(p3.y, wc.y, fmaf(p3.z, wc.z, z1[o])));
        }
    }

    const uint4* __restrict__ colb = g_xh + ((b * 513) << 9);
    float hb = (float)h * (1.f / 511.f);
    float vb2_0 = s_b2[0], vb2_1 = s_b2[1];
    float out2 = fmaxf(s_b2[2], 0.f);             // channel 2 is constant

    float o0[2], o1[2];
#pragma unroll
    for (int px = 0; px < 2; px++) {
        float* z = px ? z1 : z0;
        float s[8];
#pragma unroll
        for (int o = 0; o < 8; o++)
            s[o] = __fdividef(1.f, 1.f + __expf(-z[o]));
        float wb = (float)(w + px) * (1.f / 511.f);

        float a0 = 0.f, a1 = 0.f;
        samp(colb, hb + s[0], wb + s[1], s_w2v[0], a0);   // k=0
        samp(colb, hb + s[2], wb + s[3], s_w2v[1], a0);   // k=1
        samp(colb, hb + s[4], wb + s[5], s_w2v[2], a0);   // k=2
        samp(colb, hb + s[6], wb + s[7], s_w2v[3], a1);   // k=3
        samp(colb, hb,        wb,        s_w2v[4], a1);   // k=4 center
        o0[px] = fmaxf(a0 + vb2_0, 0.f);
        o1[px] = fmaxf(a1 + vb2_1, 0.f);
    }

    // ---- stores: float2 per channel (w even -> 8B aligned) ----
    int po = b * 3 * HWSZ + (h << 9) + w;
    *reinterpret_cast<float2*>(out + po)            = make_float2(o0[0], o0[1]);
    *reinterpret_cast<float2*>(out + po + HWSZ)     = make_float2(o1[0], o1[1]);
    *reinterpret_cast<float2*>(out + po + 2 * HWSZ) = make_float2(out2, out2);
}

// ---------------------------------------------------------------------------
extern "C" void kernel_launch(void* const* d_in, const int* in_sizes, int n_in,
                              void* d_out, int out_size) {
    const float* x  = (const float*)d_in[0];
    const float* w1 = (const float*)d_in[1];
    const float* b1 = (const float*)d_in[2];
    const float* w2 = (const float*)d_in[3];
    const float* b2 = (const float*)d_in[4];
    float* out = (float*)d_out;

    k_prep<<<dim3(16, 16, NB), dim3(32, 8)>>>(x);
    k_seesaw<<<dim3(2, 512, NB), 128>>>(w1, b1, w2, b2, out);
}